// round 5
// baseline (speedup 1.0000x reference)
#include <cuda_runtime.h>
#include <math_constants.h>

#define BN_EPS 1e-3f
#define NPTS 2048
#define NBATCH 8
#define NROWS (NPTS * NBATCH)
#define KNN 16

typedef unsigned long long u64;

__device__ float g_xcat[NROWS * 512];
__device__ float g_ytb[NROWS * 512];
__device__ float g_sq[NROWS];
__device__ int   g_idx[NROWS * KNN];

// ---------------- f32x2 packed helpers (FFMA2: 2x fp32 throughput) ----------
__device__ __forceinline__ void ffma2(u64& d, u64 a, u64 b) {
    asm("fma.rn.f32x2 %0, %1, %2, %0;" : "+l"(d) : "l"(a), "l"(b));
}
__device__ __forceinline__ float2 unpack2(u64 v) {
    float2 r;
    asm("mov.b64 {%0, %1}, %2;" : "=f"(r.x), "=f"(r.y) : "l"(v));
    return r;
}

// ---------------------------------------------------------------------------
__global__ void sqnorm_kernel(const float* __restrict__ x, int lda, int C,
                              float* __restrict__ sq) {
    int i = blockIdx.x * blockDim.x + threadIdx.x;
    if (i < NROWS) {
        const float* p = x + (long long)i * lda;
        float s = 0.f;
        for (int c = 0; c < C; c++) { float v = p[c]; s = fmaf(v, v, s); }
        sq[i] = s;
    }
}

// ---------------------------------------------------------------------------
__device__ __forceinline__ void topk_ins(float (&v)[16], int (&id)[16],
                                         float& vmin, int& vminid, int& minpos,
                                         float pv, int jg) {
    if (pv > vmin || (pv == vmin && jg < vminid)) {
#pragma unroll
        for (int q = 0; q < 16; q++)
            if (q == minpos) { v[q] = pv; id[q] = jg; }
        vmin = v[0]; vminid = id[0]; minpos = 0;
#pragma unroll
        for (int q = 1; q < 16; q++) {
            bool w = (v[q] < vmin) || (v[q] == vmin && id[q] > vminid);
            if (w) { vmin = v[q]; vminid = id[q]; minpos = q; }
        }
    }
}

// ---------------------------------------------------------------------------
// kNN: 64 i x 256 j tiles, 256 threads, micro 4i(dup) x 16j in f32x2.
// C chunked by 64 through xjT. pd = 2*dot - sq_i - sq_j; top-16 per row.
// ---------------------------------------------------------------------------
template <int C>
__global__ void knn_kernel(const float* __restrict__ x, int lda,
                           const float* __restrict__ sq, int* __restrict__ outidx) {
    constexpr int CC = (C < 64) ? C : 64;
    constexpr int NCH = (C + CC - 1) / CC;
    extern __shared__ float sm[];
    float* xiD = sm;                   // C x 136 (dup: xiD[c*136+2i]=xiD[+1]=xi)
    float* xjT = sm + C * 136;         // CC x 260
    float* pd  = xjT + CC * 260;       // 64 x 260

    const int rowbase = blockIdx.y * NPTS;
    const int i0 = blockIdx.x * 64;
    const int tid = threadIdx.x;
    const int ty = tid >> 4, tx = tid & 15;
    const int srow = tid >> 2, sq4 = tid & 3;

    for (int t = tid; t < 64 * C; t += 256) {
        int i = t / C, c = t - i * C;
        float val = x[(long long)(rowbase + i0 + i) * lda + c];
        xiD[c * 136 + 2 * i] = val;
        xiD[c * 136 + 2 * i + 1] = val;
    }
    float sqi[4];
#pragma unroll
    for (int r = 0; r < 4; r++) sqi[r] = sq[rowbase + i0 + ty * 4 + r];

    float v[16]; int id[16];
#pragma unroll
    for (int q = 0; q < 16; q++) { v[q] = -CUDART_INF_F; id[q] = 0x7fffffff; }
    float vmin = -CUDART_INF_F; int vminid = 0x7fffffff; int minpos = 0;

    const float* xjp = xjT + tx * 16;

    for (int jt = 0; jt < NPTS / 256; jt++) {
        const int j0 = jt * 256;
        u64 acc[4][8];
#pragma unroll
        for (int r = 0; r < 4; r++)
#pragma unroll
            for (int j = 0; j < 8; j++) acc[r][j] = 0ull;

#pragma unroll
        for (int ch = 0; ch < NCH; ch++) {
            const int cb = ch * CC;
            __syncthreads();   // prev consumers of xjT / pd done
            for (int t = tid; t < 256 * CC; t += 256) {
                int j = t / CC, c = t - j * CC;
                xjT[c * 260 + j] = x[(long long)(rowbase + j0 + j) * lda + cb + c];
            }
            __syncthreads();
            const float* xip = xiD + cb * 136 + ty * 8;
#pragma unroll 4
            for (int c = 0; c < CC; c++) {
                ulonglong2 a01 = *(const ulonglong2*)(xip + c * 136);
                ulonglong2 a23 = *(const ulonglong2*)(xip + c * 136 + 4);
                ulonglong2 b0 = *(const ulonglong2*)(xjp + c * 260);
                ulonglong2 b1 = *(const ulonglong2*)(xjp + c * 260 + 4);
                ulonglong2 b2 = *(const ulonglong2*)(xjp + c * 260 + 8);
                ulonglong2 b3 = *(const ulonglong2*)(xjp + c * 260 + 12);
                ffma2(acc[0][0], a01.x, b0.x); ffma2(acc[0][1], a01.x, b0.y);
                ffma2(acc[0][2], a01.x, b1.x); ffma2(acc[0][3], a01.x, b1.y);
                ffma2(acc[0][4], a01.x, b2.x); ffma2(acc[0][5], a01.x, b2.y);
                ffma2(acc[0][6], a01.x, b3.x); ffma2(acc[0][7], a01.x, b3.y);
                ffma2(acc[1][0], a01.y, b0.x); ffma2(acc[1][1], a01.y, b0.y);
                ffma2(acc[1][2], a01.y, b1.x); ffma2(acc[1][3], a01.y, b1.y);
                ffma2(acc[1][4], a01.y, b2.x); ffma2(acc[1][5], a01.y, b2.y);
                ffma2(acc[1][6], a01.y, b3.x); ffma2(acc[1][7], a01.y, b3.y);
                ffma2(acc[2][0], a23.x, b0.x); ffma2(acc[2][1], a23.x, b0.y);
                ffma2(acc[2][2], a23.x, b1.x); ffma2(acc[2][3], a23.x, b1.y);
                ffma2(acc[2][4], a23.x, b2.x); ffma2(acc[2][5], a23.x, b2.y);
                ffma2(acc[2][6], a23.x, b3.x); ffma2(acc[2][7], a23.x, b3.y);
                ffma2(acc[3][0], a23.y, b0.x); ffma2(acc[3][1], a23.y, b0.y);
                ffma2(acc[3][2], a23.y, b1.x); ffma2(acc[3][3], a23.y, b1.y);
                ffma2(acc[3][4], a23.y, b2.x); ffma2(acc[3][5], a23.y, b2.y);
                ffma2(acc[3][6], a23.y, b3.x); ffma2(acc[3][7], a23.y, b3.y);
            }
        }

        // epilogue: pd = 2*dot - sqi - sqj -> shared
        float4 sj[4];
#pragma unroll
        for (int s = 0; s < 4; s++)
            sj[s] = *(const float4*)&sq[rowbase + j0 + tx * 16 + s * 4];
#pragma unroll
        for (int r = 0; r < 4; r++) {
#pragma unroll
            for (int s = 0; s < 4; s++) {
                float2 lo = unpack2(acc[r][2 * s]);
                float2 hi = unpack2(acc[r][2 * s + 1]);
                float4 o;
                o.x = 2.f * lo.x - sqi[r] - sj[s].x;
                o.y = 2.f * lo.y - sqi[r] - sj[s].y;
                o.z = 2.f * hi.x - sqi[r] - sj[s].z;
                o.w = 2.f * hi.y - sqi[r] - sj[s].w;
                *(float4*)&pd[(ty * 4 + r) * 260 + tx * 16 + s * 4] = o;
            }
        }
        __syncthreads();

        // selection: thread (srow, sq4) scans j strip [sq4*64, sq4*64+64)
#pragma unroll
        for (int s = 0; s < 16; s++) {
            const float4 pv = *(const float4*)&pd[srow * 260 + sq4 * 64 + s * 4];
            int jb = j0 + sq4 * 64 + s * 4;
            topk_ins(v, id, vmin, vminid, minpos, pv.x, jb);
            topk_ins(v, id, vmin, vminid, minpos, pv.y, jb + 1);
            topk_ins(v, id, vmin, vminid, minpos, pv.z, jb + 2);
            topk_ins(v, id, vmin, vminid, minpos, pv.w, jb + 3);
        }
    }

    // merge 4 lanes x 16 entries -> top-16 per row via warp shuffles
    for (int t = 0; t < KNN; t++) {
        float bv = -CUDART_INF_F; int bid = 0x7fffffff; int bq = 0;
#pragma unroll
        for (int q = 0; q < 16; q++) {
            bool w = (v[q] > bv) || (v[q] == bv && id[q] < bid);
            if (w) { bv = v[q]; bid = id[q]; bq = q; }
        }
        float lv = bv; int lid = bid;
#pragma unroll
        for (int off = 1; off < 4; off <<= 1) {
            float ov = __shfl_xor_sync(0xffffffffu, bv, off);
            int oid = __shfl_xor_sync(0xffffffffu, bid, off);
            if (ov > bv || (ov == bv && oid < bid)) { bv = ov; bid = oid; }
        }
        if (lid == bid && lv == bv) { v[bq] = -CUDART_INF_F; id[bq] = 0x7fffffff; }
        if (sq4 == 0) outidx[(long long)(rowbase + i0 + srow) * KNN + t] = bid;
    }
}

// ---------------------------------------------------------------------------
// SGEMM 128x128x16, 256 threads, micro 8m(dup)x8n in f32x2, double-buffered.
// dual: out [rows,2D] = A @ [Wtop|Wbot]. Optional fused BN+ReLU.
// ---------------------------------------------------------------------------
__global__ void sgemm_kernel(const float* __restrict__ A, int lda,
                             const float* __restrict__ W, int K, int D, int dual,
                             float* __restrict__ Co, int ldc,
                             const float* __restrict__ bg, const float* __restrict__ bb,
                             const float* __restrict__ bm, const float* __restrict__ bvv) {
    extern __shared__ float smg[];
    float* As = smg;                   // 2 x 16 x 260 (128 m dup + pad)
    float* Bs = smg + 2 * 16 * 260;    // 2 x 16 x 132
    const int mb = blockIdx.y * 128, nb = blockIdx.x * 128;
    const int tid = threadIdx.x;
    const int ry = tid >> 4, rx = tid & 15;
    u64 acc[8][4];
#pragma unroll
    for (int r = 0; r < 8; r++)
#pragma unroll
        for (int j = 0; j < 4; j++) acc[r][j] = 0ull;
    float ra[8], rb[8];

#pragma unroll
    for (int u = 0; u < 8; u++) {
        int t = tid + u * 256; int m = t >> 4, k = t & 15;
        ra[u] = (k < K) ? A[(long long)(mb + m) * lda + k] : 0.f;
    }
#pragma unroll
    for (int u = 0; u < 8; u++) {
        int t = tid + u * 256; int k = t >> 7, n = t & 127;
        int gn = nb + n;
        float val = 0.f;
        if (k < K) {
            if (!dual) val = W[(long long)k * D + gn];
            else if (gn < D) val = W[(long long)k * D + gn];
            else val = W[(long long)(K + k) * D + gn - D];
        }
        rb[u] = val;
    }
#pragma unroll
    for (int u = 0; u < 8; u++) {
        int t = tid + u * 256;
        As[(t & 15) * 260 + 2 * (t >> 4)] = ra[u];
        As[(t & 15) * 260 + 2 * (t >> 4) + 1] = ra[u];
        Bs[(t >> 7) * 132 + (t & 127)] = rb[u];
    }
    __syncthreads();

    int p = 0;
    for (int kt = 0; kt < K; kt += 16) {
        const bool more = (kt + 16 < K);
        if (more) {
#pragma unroll
            for (int u = 0; u < 8; u++) {
                int t = tid + u * 256; int m = t >> 4, k = kt + 16 + (t & 15);
                ra[u] = (k < K) ? A[(long long)(mb + m) * lda + k] : 0.f;
            }
#pragma unroll
            for (int u = 0; u < 8; u++) {
                int t = tid + u * 256; int k = kt + 16 + (t >> 7), n = t & 127;
                int gn = nb + n;
                float val = 0.f;
                if (k < K) {
                    if (!dual) val = W[(long long)k * D + gn];
                    else if (gn < D) val = W[(long long)k * D + gn];
                    else val = W[(long long)(K + k) * D + gn - D];
                }
                rb[u] = val;
            }
        }
        const float* ap = As + p * 16 * 260 + ry * 16;
        const float* bp = Bs + p * 16 * 132 + rx * 8;
#pragma unroll
        for (int k = 0; k < 16; k++) {
            ulonglong2 a01 = *(const ulonglong2*)(ap + k * 260);
            ulonglong2 a23 = *(const ulonglong2*)(ap + k * 260 + 4);
            ulonglong2 a45 = *(const ulonglong2*)(ap + k * 260 + 8);
            ulonglong2 a67 = *(const ulonglong2*)(ap + k * 260 + 12);
            ulonglong2 b01 = *(const ulonglong2*)(bp + k * 132);
            ulonglong2 b23 = *(const ulonglong2*)(bp + k * 132 + 4);
            ffma2(acc[0][0], a01.x, b01.x); ffma2(acc[0][1], a01.x, b01.y);
            ffma2(acc[0][2], a01.x, b23.x); ffma2(acc[0][3], a01.x, b23.y);
            ffma2(acc[1][0], a01.y, b01.x); ffma2(acc[1][1], a01.y, b01.y);
            ffma2(acc[1][2], a01.y, b23.x); ffma2(acc[1][3], a01.y, b23.y);
            ffma2(acc[2][0], a23.x, b01.x); ffma2(acc[2][1], a23.x, b01.y);
            ffma2(acc[2][2], a23.x, b23.x); ffma2(acc[2][3], a23.x, b23.y);
            ffma2(acc[3][0], a23.y, b01.x); ffma2(acc[3][1], a23.y, b01.y);
            ffma2(acc[3][2], a23.y, b23.x); ffma2(acc[3][3], a23.y, b23.y);
            ffma2(acc[4][0], a45.x, b01.x); ffma2(acc[4][1], a45.x, b01.y);
            ffma2(acc[4][2], a45.x, b23.x); ffma2(acc[4][3], a45.x, b23.y);
            ffma2(acc[5][0], a45.y, b01.x); ffma2(acc[5][1], a45.y, b01.y);
            ffma2(acc[5][2], a45.y, b23.x); ffma2(acc[5][3], a45.y, b23.y);
            ffma2(acc[6][0], a67.x, b01.x); ffma2(acc[6][1], a67.x, b01.y);
            ffma2(acc[6][2], a67.x, b23.x); ffma2(acc[6][3], a67.x, b23.y);
            ffma2(acc[7][0], a67.y, b01.x); ffma2(acc[7][1], a67.y, b01.y);
            ffma2(acc[7][2], a67.y, b23.x); ffma2(acc[7][3], a67.y, b23.y);
        }
        if (more) {
            __syncthreads();
#pragma unroll
            for (int u = 0; u < 8; u++) {
                int t = tid + u * 256;
                As[(p ^ 1) * 16 * 260 + (t & 15) * 260 + 2 * (t >> 4)] = ra[u];
                As[(p ^ 1) * 16 * 260 + (t & 15) * 260 + 2 * (t >> 4) + 1] = ra[u];
                Bs[(p ^ 1) * 16 * 132 + (t >> 7) * 132 + (t & 127)] = rb[u];
            }
            __syncthreads();
            p ^= 1;
        }
    }

    float out[8][8];
#pragma unroll
    for (int i = 0; i < 8; i++)
#pragma unroll
        for (int j = 0; j < 4; j++) {
            float2 d2 = unpack2(acc[i][j]);
            out[i][2 * j] = d2.x; out[i][2 * j + 1] = d2.y;
        }
    if (bg) {
#pragma unroll
        for (int j = 0; j < 8; j++) {
            int n = nb + rx * 8 + j;
            float s = bg[n] * rsqrtf(bvv[n] + BN_EPS);
            float t = bb[n] - bm[n] * s;
#pragma unroll
            for (int i = 0; i < 8; i++) out[i][j] = fmaxf(fmaf(out[i][j], s, t), 0.f);
        }
    }
#pragma unroll
    for (int i = 0; i < 8; i++) {
        float* cp = Co + (long long)(mb + ry * 8 + i) * ldc + nb + rx * 8;
        *(float4*)cp = make_float4(out[i][0], out[i][1], out[i][2], out[i][3]);
        *(float4*)(cp + 4) = make_float4(out[i][4], out[i][5], out[i][6], out[i][7]);
    }
}

// ---------------------------------------------------------------------------
// gather + BN + ReLU + max over k=16; fused next-stage sqnorm. Warp per row.
// ---------------------------------------------------------------------------
__global__ void gathermax_kernel(const float* __restrict__ ytb, const int* __restrict__ idx,
                                 int D,
                                 const float* __restrict__ g, const float* __restrict__ b,
                                 const float* __restrict__ m, const float* __restrict__ vv,
                                 float* __restrict__ out, float* __restrict__ sqout) {
    const int warp = (blockIdx.x * blockDim.x + threadIdx.x) >> 5;
    const int lane = threadIdx.x & 31;
    if (warp >= NROWS) return;
    const int row = warp;
    const int base = row & ~(NPTS - 1);
    const int myid = idx[(long long)row * KNN + (lane & 15)];
    const float* top = ytb + (long long)row * 2 * D;
    float ss = 0.f;
    for (int c0 = 0; c0 < D; c0 += 64) {
        const int d = c0 + lane * 2;
        float2 g2 = *(const float2*)&g[d];
        float2 v2 = *(const float2*)&vv[d];
        float2 b2 = *(const float2*)&b[d];
        float2 m2 = *(const float2*)&m[d];
        float sx = g2.x * rsqrtf(v2.x + BN_EPS), txx = b2.x - m2.x * sx;
        float sy = g2.y * rsqrtf(v2.y + BN_EPS), tyy = b2.y - m2.y * sy;
        float2 tp = *(const float2*)&top[d];
        float bx = -CUDART_INF_F, by = -CUDART_INF_F;
#pragma unroll
        for (int k = 0; k < KNN; k++) {
            int sk = __shfl_sync(0xffffffffu, myid, k, 16);
            float2 yb = *(const float2*)&ytb[(long long)(base + sk) * 2 * D + D + d];
            bx = fmaxf(bx, fmaf(tp.x + yb.x, sx, txx));
            by = fmaxf(by, fmaf(tp.y + yb.y, sy, tyy));
        }
        bx = fmaxf(bx, 0.f); by = fmaxf(by, 0.f);
        *(float2*)&out[(long long)row * 512 + d] = make_float2(bx, by);
        ss += bx * bx + by * by;
    }
#pragma unroll
    for (int off = 16; off > 0; off >>= 1) ss += __shfl_down_sync(0xffffffffu, ss, off);
    if (lane == 0) sqout[row] = ss;
}

// ---------------------------------------------------------------------------
template <int C>
static void launch_knn(const float* in, int lda, const float* sqp, int* idxp) {
    constexpr int CC = (C < 64) ? C : 64;
    size_t smem = (size_t)(C * 136 + CC * 260 + 64 * 260) * 4;
    static bool done = false;
    if (!done) {
        cudaFuncSetAttribute(knn_kernel<C>, cudaFuncAttributeMaxDynamicSharedMemorySize,
                             (int)smem);
        done = true;
    }
    knn_kernel<C><<<dim3(NPTS / 64, NBATCH), 256, smem>>>(in, lda, sqp, idxp);
}

extern "C" void kernel_launch(void* const* d_in, const int* in_sizes, int n_in,
                              void* d_out, int out_size) {
    const float* x = (const float*)d_in[0];
    const float *W[5], *gg[5], *bb[5], *mm[5], *vv[5];
    for (int i = 0; i < 5; i++) {
        W[i]  = (const float*)d_in[1 + 5 * i];
        gg[i] = (const float*)d_in[2 + 5 * i];
        bb[i] = (const float*)d_in[3 + 5 * i];
        mm[i] = (const float*)d_in[4 + 5 * i];
        vv[i] = (const float*)d_in[5 + 5 * i];
    }
    float *xcat, *ytb, *sqp; int* idxp;
    cudaGetSymbolAddress((void**)&xcat, g_xcat);
    cudaGetSymbolAddress((void**)&ytb, g_ytb);
    cudaGetSymbolAddress((void**)&sqp, g_sq);
    cudaGetSymbolAddress((void**)&idxp, g_idx);

    const size_t gemm_smem = (size_t)(2 * 16 * 260 + 2 * 16 * 132) * 4;
    static bool ginit = false;
    if (!ginit) {
        cudaFuncSetAttribute(sgemm_kernel, cudaFuncAttributeMaxDynamicSharedMemorySize,
                             (int)gemm_smem);
        ginit = true;
    }

    const int Cs[4] = {3, 64, 64, 128};
    const int Ds[4] = {64, 64, 128, 256};

    sqnorm_kernel<<<NROWS / 256, 256>>>(x, 3, 3, sqp);

    const float* in = x;
    int lda = 3;
    int coloff = 0;
    for (int s = 0; s < 4; s++) {
        const int C = Cs[s], D = Ds[s];
        if (C == 3)        launch_knn<3>(in, lda, sqp, idxp);
        else if (C == 64)  launch_knn<64>(in, lda, sqp, idxp);
        else               launch_knn<128>(in, lda, sqp, idxp);
        sgemm_kernel<<<dim3(2 * D / 128, NROWS / 128), 256, gemm_smem>>>(
            in, lda, W[s], C, D, 1, ytb, 2 * D, nullptr, nullptr, nullptr, nullptr);
        float* outp = xcat + coloff;
        gathermax_kernel<<<NROWS / 8, 256>>>(ytb, idxp, D, gg[s], bb[s], mm[s], vv[s],
                                             outp, sqp);
        in = outp; lda = 512;
        coloff += D;
    }
    sgemm_kernel<<<dim3(512 / 128, NROWS / 128), 256, gemm_smem>>>(
        xcat, 512, W[4], 512, 512, 0, (float*)d_out, 512,
        gg[4], bb[4], mm[4], vv[4]);
}

// round 6
// speedup vs baseline: 3.1339x; 3.1339x over previous
#include <cuda_runtime.h>
#include <math_constants.h>

#define BN_EPS 1e-3f
#define NPTS 2048
#define NBATCH 8
#define NROWS (NPTS * NBATCH)
#define KNN 16

typedef unsigned long long u64;

__device__ float g_xcat[NROWS * 512];
__device__ float g_ytb[NROWS * 512];
__device__ float g_sq[NROWS];
__device__ int   g_idx[NROWS * KNN];

// ---------------- f32x2 packed helpers (FFMA2: 2x fp32 throughput) ----------
__device__ __forceinline__ void ffma2(u64& d, u64 a, u64 b) {
    asm("fma.rn.f32x2 %0, %1, %2, %0;" : "+l"(d) : "l"(a), "l"(b));
}
__device__ __forceinline__ float2 unpack2(u64 v) {
    float2 r;
    asm("mov.b64 {%0, %1}, %2;" : "=f"(r.x), "=f"(r.y) : "l"(v));
    return r;
}

// ---------------------------------------------------------------------------
__global__ void sqnorm_kernel(const float* __restrict__ x, int lda, int C,
                              float* __restrict__ sq) {
    int i = blockIdx.x * blockDim.x + threadIdx.x;
    if (i < NROWS) {
        const float* p = x + (long long)i * lda;
        float s = 0.f;
        for (int c = 0; c < C; c++) { float v = p[c]; s = fmaf(v, v, s); }
        sq[i] = s;
    }
}

// ---------------------------------------------------------------------------
__device__ __forceinline__ void topk_ins(float (&v)[16], int (&id)[16],
                                         float& vmin, int& vminid, int& minpos,
                                         float pv, int jg) {
    if (pv > vmin || (pv == vmin && jg < vminid)) {
#pragma unroll
        for (int q = 0; q < 16; q++)
            if (q == minpos) { v[q] = pv; id[q] = jg; }
        vmin = v[0]; vminid = id[0]; minpos = 0;
#pragma unroll
        for (int q = 1; q < 16; q++) {
            bool w = (v[q] < vmin) || (v[q] == vmin && id[q] > vminid);
            if (w) { vmin = v[q]; vminid = id[q]; minpos = q; }
        }
    }
}

// ---------------------------------------------------------------------------
// kNN: 64 i x 128 j tiles, 256 threads, micro 4i(dup) x 8j in f32x2.
// acc[4][4] u64 = 32 regs (spill-safe with 32 top-k regs live).
// xiD holds xi duplicated so (a,a) pairs load as LDS.128.
// pd = 2*dot - sq_i - sq_j; top-16 per row, ties -> lower index.
// ---------------------------------------------------------------------------
template <int C>
__global__ void knn_kernel(const float* __restrict__ x, int lda,
                           const float* __restrict__ sq, int* __restrict__ outidx) {
    extern __shared__ float sm[];
    float* xiD = sm;                   // C x 136 (dup)
    float* xjT = sm + C * 136;         // C x 132 (xjT[c*132 + j], 128 j)
    float* pd  = xjT + C * 132;        // 64 x 132

    const int rowbase = blockIdx.y * NPTS;
    const int i0 = blockIdx.x * 64;
    const int tid = threadIdx.x;
    const int ty = tid >> 4, tx = tid & 15;
    const int srow = tid >> 2, sq4 = tid & 3;

    for (int t = tid; t < 64 * C; t += 256) {
        int i = t / C, c = t - i * C;
        float val = x[(long long)(rowbase + i0 + i) * lda + c];
        xiD[c * 136 + 2 * i] = val;
        xiD[c * 136 + 2 * i + 1] = val;
    }
    float sqi[4];
#pragma unroll
    for (int r = 0; r < 4; r++) sqi[r] = sq[rowbase + i0 + ty * 4 + r];

    float v[16]; int id[16];
#pragma unroll
    for (int q = 0; q < 16; q++) { v[q] = -CUDART_INF_F; id[q] = 0x7fffffff; }
    float vmin = -CUDART_INF_F; int vminid = 0x7fffffff; int minpos = 0;

    const float* xip = xiD + ty * 8;
    const float* xjp = xjT + tx * 8;

    for (int jt = 0; jt < NPTS / 128; jt++) {
        const int j0 = jt * 128;
        __syncthreads();   // prev tile consumers done
        for (int t = tid; t < 128 * C; t += 256) {
            int j = t / C, c = t - j * C;
            xjT[c * 132 + j] = x[(long long)(rowbase + j0 + j) * lda + c];
        }
        __syncthreads();

        u64 acc[4][4];
#pragma unroll
        for (int r = 0; r < 4; r++)
#pragma unroll
            for (int j = 0; j < 4; j++) acc[r][j] = 0ull;

#pragma unroll 4
        for (int c = 0; c < C; c++) {
            ulonglong2 a01 = *(const ulonglong2*)(xip + c * 136);
            ulonglong2 a23 = *(const ulonglong2*)(xip + c * 136 + 4);
            ulonglong2 b01 = *(const ulonglong2*)(xjp + c * 132);
            ulonglong2 b23 = *(const ulonglong2*)(xjp + c * 132 + 4);
            ffma2(acc[0][0], a01.x, b01.x); ffma2(acc[0][1], a01.x, b01.y);
            ffma2(acc[0][2], a01.x, b23.x); ffma2(acc[0][3], a01.x, b23.y);
            ffma2(acc[1][0], a01.y, b01.x); ffma2(acc[1][1], a01.y, b01.y);
            ffma2(acc[1][2], a01.y, b23.x); ffma2(acc[1][3], a01.y, b23.y);
            ffma2(acc[2][0], a23.x, b01.x); ffma2(acc[2][1], a23.x, b01.y);
            ffma2(acc[2][2], a23.x, b23.x); ffma2(acc[2][3], a23.x, b23.y);
            ffma2(acc[3][0], a23.y, b01.x); ffma2(acc[3][1], a23.y, b01.y);
            ffma2(acc[3][2], a23.y, b23.x); ffma2(acc[3][3], a23.y, b23.y);
        }

        // epilogue: pd = 2*dot - sqi - sqj -> shared
        float4 sjA = *(const float4*)&sq[rowbase + j0 + tx * 8];
        float4 sjB = *(const float4*)&sq[rowbase + j0 + tx * 8 + 4];
#pragma unroll
        for (int r = 0; r < 4; r++) {
            float2 p0 = unpack2(acc[r][0]);
            float2 p1 = unpack2(acc[r][1]);
            float2 p2 = unpack2(acc[r][2]);
            float2 p3 = unpack2(acc[r][3]);
            float4 oA, oB;
            oA.x = 2.f * p0.x - sqi[r] - sjA.x;
            oA.y = 2.f * p0.y - sqi[r] - sjA.y;
            oA.z = 2.f * p1.x - sqi[r] - sjA.z;
            oA.w = 2.f * p1.y - sqi[r] - sjA.w;
            oB.x = 2.f * p2.x - sqi[r] - sjB.x;
            oB.y = 2.f * p2.y - sqi[r] - sjB.y;
            oB.z = 2.f * p3.x - sqi[r] - sjB.z;
            oB.w = 2.f * p3.y - sqi[r] - sjB.w;
            *(float4*)&pd[(ty * 4 + r) * 132 + tx * 8] = oA;
            *(float4*)&pd[(ty * 4 + r) * 132 + tx * 8 + 4] = oB;
        }
        __syncthreads();

        // selection: thread (srow, sq4) scans j strip [sq4*32, sq4*32+32)
#pragma unroll
        for (int s = 0; s < 8; s++) {
            const float4 pv = *(const float4*)&pd[srow * 132 + sq4 * 32 + s * 4];
            int jb = j0 + sq4 * 32 + s * 4;
            topk_ins(v, id, vmin, vminid, minpos, pv.x, jb);
            topk_ins(v, id, vmin, vminid, minpos, pv.y, jb + 1);
            topk_ins(v, id, vmin, vminid, minpos, pv.z, jb + 2);
            topk_ins(v, id, vmin, vminid, minpos, pv.w, jb + 3);
        }
    }

    // merge 4 lanes x 16 entries -> top-16 per row via warp shuffles
    for (int t = 0; t < KNN; t++) {
        float bv = -CUDART_INF_F; int bid = 0x7fffffff; int bq = 0;
#pragma unroll
        for (int q = 0; q < 16; q++) {
            bool w = (v[q] > bv) || (v[q] == bv && id[q] < bid);
            if (w) { bv = v[q]; bid = id[q]; bq = q; }
        }
        float lv = bv; int lid = bid;
#pragma unroll
        for (int off = 1; off < 4; off <<= 1) {
            float ov = __shfl_xor_sync(0xffffffffu, bv, off);
            int oid = __shfl_xor_sync(0xffffffffu, bid, off);
            if (ov > bv || (ov == bv && oid < bid)) { bv = ov; bid = oid; }
        }
        if (lid == bid && lv == bv) { v[bq] = -CUDART_INF_F; id[bq] = 0x7fffffff; }
        if (sq4 == 0) outidx[(long long)(rowbase + i0 + srow) * KNN + t] = bid;
    }
}

// ---------------------------------------------------------------------------
// SGEMM 64x64x16, 256 threads, 4x4 micro-tile in f32x2, double-buffered.
// (identical to the round-4 version that measured well)
// ---------------------------------------------------------------------------
__global__ void sgemm_kernel(const float* __restrict__ A, int lda,
                             const float* __restrict__ W, int K, int D, int dual,
                             float* __restrict__ Co, int ldc,
                             const float* __restrict__ bg, const float* __restrict__ bb,
                             const float* __restrict__ bm, const float* __restrict__ bvv) {
    __shared__ float As[2][16 * 136];
    __shared__ float Bs[2][16 * 68];
    const int mb = blockIdx.y * 64, nb = blockIdx.x * 64;
    const int tid = threadIdx.x;
    const int ry = tid >> 4, rx = tid & 15;
    u64 acc[4][2];
#pragma unroll
    for (int r = 0; r < 4; r++) { acc[r][0] = 0ull; acc[r][1] = 0ull; }
    float ra[4], rb[4];

#pragma unroll
    for (int u = 0; u < 4; u++) {
        int t = tid + u * 256; int m = t >> 4, k = t & 15;
        ra[u] = (k < K) ? A[(long long)(mb + m) * lda + k] : 0.f;
    }
#pragma unroll
    for (int u = 0; u < 4; u++) {
        int t = tid + u * 256; int k = t >> 6, n = t & 63;
        int gn = nb + n;
        float val = 0.f;
        if (k < K) {
            if (!dual) val = W[(long long)k * D + gn];
            else if (gn < D) val = W[(long long)k * D + gn];
            else val = W[(long long)(K + k) * D + gn - D];
        }
        rb[u] = val;
    }
#pragma unroll
    for (int u = 0; u < 4; u++) {
        int t = tid + u * 256;
        As[0][(t & 15) * 136 + 2 * (t >> 4)] = ra[u];
        As[0][(t & 15) * 136 + 2 * (t >> 4) + 1] = ra[u];
        Bs[0][(t >> 6) * 68 + (t & 63)] = rb[u];
    }
    __syncthreads();

    int p = 0;
    for (int kt = 0; kt < K; kt += 16) {
        const bool more = (kt + 16 < K);
        if (more) {
#pragma unroll
            for (int u = 0; u < 4; u++) {
                int t = tid + u * 256; int m = t >> 4, k = kt + 16 + (t & 15);
                ra[u] = (k < K) ? A[(long long)(mb + m) * lda + k] : 0.f;
            }
#pragma unroll
            for (int u = 0; u < 4; u++) {
                int t = tid + u * 256; int k = kt + 16 + (t >> 6), n = t & 63;
                int gn = nb + n;
                float val = 0.f;
                if (k < K) {
                    if (!dual) val = W[(long long)k * D + gn];
                    else if (gn < D) val = W[(long long)k * D + gn];
                    else val = W[(long long)(K + k) * D + gn - D];
                }
                rb[u] = val;
            }
        }
#pragma unroll
        for (int k = 0; k < 16; k++) {
            ulonglong2 a01 = *(const ulonglong2*)&As[p][k * 136 + ry * 8];
            ulonglong2 a23 = *(const ulonglong2*)&As[p][k * 136 + ry * 8 + 4];
            ulonglong2 bq  = *(const ulonglong2*)&Bs[p][k * 68 + rx * 4];
            ffma2(acc[0][0], a01.x, bq.x); ffma2(acc[0][1], a01.x, bq.y);
            ffma2(acc[1][0], a01.y, bq.x); ffma2(acc[1][1], a01.y, bq.y);
            ffma2(acc[2][0], a23.x, bq.x); ffma2(acc[2][1], a23.x, bq.y);
            ffma2(acc[3][0], a23.y, bq.x); ffma2(acc[3][1], a23.y, bq.y);
        }
        if (more) {
            __syncthreads();
#pragma unroll
            for (int u = 0; u < 4; u++) {
                int t = tid + u * 256;
                As[p ^ 1][(t & 15) * 136 + 2 * (t >> 4)] = ra[u];
                As[p ^ 1][(t & 15) * 136 + 2 * (t >> 4) + 1] = ra[u];
                Bs[p ^ 1][(t >> 6) * 68 + (t & 63)] = rb[u];
            }
            __syncthreads();
            p ^= 1;
        }
    }

    float out[4][4];
#pragma unroll
    for (int i = 0; i < 4; i++) {
        float2 lo = unpack2(acc[i][0]);
        float2 hi = unpack2(acc[i][1]);
        out[i][0] = lo.x; out[i][1] = lo.y; out[i][2] = hi.x; out[i][3] = hi.y;
    }
    if (bg) {
#pragma unroll
        for (int j = 0; j < 4; j++) {
            int n = nb + rx * 4 + j;
            float s = bg[n] * rsqrtf(bvv[n] + BN_EPS);
            float t = bb[n] - bm[n] * s;
#pragma unroll
            for (int i = 0; i < 4; i++) out[i][j] = fmaxf(fmaf(out[i][j], s, t), 0.f);
        }
    }
#pragma unroll
    for (int i = 0; i < 4; i++) {
        *(float4*)&Co[(long long)(mb + ry * 4 + i) * ldc + nb + rx * 4] =
            make_float4(out[i][0], out[i][1], out[i][2], out[i][3]);
    }
}

// ---------------------------------------------------------------------------
// gather + BN + ReLU + max over k=16; fused next-stage sqnorm. Warp per row.
// ---------------------------------------------------------------------------
__global__ void gathermax_kernel(const float* __restrict__ ytb, const int* __restrict__ idx,
                                 int D,
                                 const float* __restrict__ g, const float* __restrict__ b,
                                 const float* __restrict__ m, const float* __restrict__ vv,
                                 float* __restrict__ out, float* __restrict__ sqout) {
    const int warp = (blockIdx.x * blockDim.x + threadIdx.x) >> 5;
    const int lane = threadIdx.x & 31;
    if (warp >= NROWS) return;
    const int row = warp;
    const int base = row & ~(NPTS - 1);
    const int myid = idx[(long long)row * KNN + (lane & 15)];
    const float* top = ytb + (long long)row * 2 * D;
    float ss = 0.f;
    for (int c0 = 0; c0 < D; c0 += 64) {
        const int d = c0 + lane * 2;
        float2 g2 = *(const float2*)&g[d];
        float2 v2 = *(const float2*)&vv[d];
        float2 b2 = *(const float2*)&b[d];
        float2 m2 = *(const float2*)&m[d];
        float sx = g2.x * rsqrtf(v2.x + BN_EPS), txx = b2.x - m2.x * sx;
        float sy = g2.y * rsqrtf(v2.y + BN_EPS), tyy = b2.y - m2.y * sy;
        float2 tp = *(const float2*)&top[d];
        float bx = -CUDART_INF_F, by = -CUDART_INF_F;
#pragma unroll
        for (int k = 0; k < KNN; k++) {
            int sk = __shfl_sync(0xffffffffu, myid, k, 16);
            float2 yb = *(const float2*)&ytb[(long long)(base + sk) * 2 * D + D + d];
            bx = fmaxf(bx, fmaf(tp.x + yb.x, sx, txx));
            by = fmaxf(by, fmaf(tp.y + yb.y, sy, tyy));
        }
        bx = fmaxf(bx, 0.f); by = fmaxf(by, 0.f);
        *(float2*)&out[(long long)row * 512 + d] = make_float2(bx, by);
        ss += bx * bx + by * by;
    }
#pragma unroll
    for (int off = 16; off > 0; off >>= 1) ss += __shfl_down_sync(0xffffffffu, ss, off);
    if (lane == 0) sqout[row] = ss;
}

// ---------------------------------------------------------------------------
template <int C>
static void launch_knn(const float* in, int lda, const float* sqp, int* idxp) {
    size_t smem = (size_t)(C * 136 + C * 132 + 64 * 132) * 4;
    static bool done = false;
    if (!done) {
        cudaFuncSetAttribute(knn_kernel<C>, cudaFuncAttributeMaxDynamicSharedMemorySize,
                             (int)smem);
        done = true;
    }
    knn_kernel<C><<<dim3(NPTS / 64, NBATCH), 256, smem>>>(in, lda, sqp, idxp);
}

extern "C" void kernel_launch(void* const* d_in, const int* in_sizes, int n_in,
                              void* d_out, int out_size) {
    const float* x = (const float*)d_in[0];
    const float *W[5], *gg[5], *bb[5], *mm[5], *vv[5];
    for (int i = 0; i < 5; i++) {
        W[i]  = (const float*)d_in[1 + 5 * i];
        gg[i] = (const float*)d_in[2 + 5 * i];
        bb[i] = (const float*)d_in[3 + 5 * i];
        mm[i] = (const float*)d_in[4 + 5 * i];
        vv[i] = (const float*)d_in[5 + 5 * i];
    }
    float *xcat, *ytb, *sqp; int* idxp;
    cudaGetSymbolAddress((void**)&xcat, g_xcat);
    cudaGetSymbolAddress((void**)&ytb, g_ytb);
    cudaGetSymbolAddress((void**)&sqp, g_sq);
    cudaGetSymbolAddress((void**)&idxp, g_idx);

    const int Cs[4] = {3, 64, 64, 128};
    const int Ds[4] = {64, 64, 128, 256};

    sqnorm_kernel<<<NROWS / 256, 256>>>(x, 3, 3, sqp);

    const float* in = x;
    int lda = 3;
    int coloff = 0;
    for (int s = 0; s < 4; s++) {
        const int C = Cs[s], D = Ds[s];
        if (C == 3)        launch_knn<3>(in, lda, sqp, idxp);
        else if (C == 64)  launch_knn<64>(in, lda, sqp, idxp);
        else               launch_knn<128>(in, lda, sqp, idxp);
        sgemm_kernel<<<dim3(2 * D / 64, NROWS / 64), 256>>>(in, lda, W[s], C, D, 1,
                                                            ytb, 2 * D,
                                                            nullptr, nullptr, nullptr, nullptr);
        float* outp = xcat + coloff;
        gathermax_kernel<<<NROWS / 8, 256>>>(ytb, idxp, D, gg[s], bb[s], mm[s], vv[s],
                                             outp, sqp);
        in = outp; lda = 512;
        coloff += D;
    }
    sgemm_kernel<<<dim3(512 / 64, NROWS / 64), 256>>>(xcat, 512, W[4], 512, 512, 0,
                                                      (float*)d_out, 512,
                                                      gg[4], bb[4], mm[4], vv[4]);
}

// round 7
// speedup vs baseline: 3.2888x; 1.0494x over previous
#include <cuda_runtime.h>
#include <math_constants.h>

#define BN_EPS 1e-3f
#define NPTS 2048
#define NBATCH 8
#define NROWS (NPTS * NBATCH)
#define KNN 16

typedef unsigned long long u64;

__device__ float g_xcat[NROWS * 512];
__device__ float g_ytb[NROWS * 512];
__device__ float g_sq[NROWS];
__device__ int   g_idx[NROWS * KNN];

// ---------------- f32x2 packed helpers (FFMA2: 2x fp32 throughput) ----------
__device__ __forceinline__ void ffma2(u64& d, u64 a, u64 b) {
    asm("fma.rn.f32x2 %0, %1, %2, %0;" : "+l"(d) : "l"(a), "l"(b));
}
__device__ __forceinline__ float2 unpack2(u64 v) {
    float2 r;
    asm("mov.b64 {%0, %1}, %2;" : "=f"(r.x), "=f"(r.y) : "l"(v));
    return r;
}

// ---------------------------------------------------------------------------
__global__ void sqnorm_kernel(const float* __restrict__ x, int lda, int C,
                              float* __restrict__ sq) {
    int i = blockIdx.x * blockDim.x + threadIdx.x;
    if (i < NROWS) {
        const float* p = x + (long long)i * lda;
        float s = 0.f;
        for (int c = 0; c < C; c++) { float v = p[c]; s = fmaf(v, v, s); }
        sq[i] = s;
    }
}

// ---------------------------------------------------------------------------
__device__ __forceinline__ void topk_ins(float (&v)[16], int (&id)[16],
                                         float& vmin, int& vminid, int& minpos,
                                         float pv, int jg) {
    if (pv > vmin || (pv == vmin && jg < vminid)) {
#pragma unroll
        for (int q = 0; q < 16; q++)
            if (q == minpos) { v[q] = pv; id[q] = jg; }
        vmin = v[0]; vminid = id[0]; minpos = 0;
#pragma unroll
        for (int q = 1; q < 16; q++) {
            bool w = (v[q] < vmin) || (v[q] == vmin && id[q] > vminid);
            if (w) { vmin = v[q]; vminid = id[q]; minpos = q; }
        }
    }
}

// ---------------------------------------------------------------------------
// kNN: 64 i x 128 j tiles, 256 threads, micro 4i(dup) x 8j (split j-strips).
// Thread's j columns: {tx*4..+3} and {64+tx*4..+3} -> both LDS.128 loads are
// 16B-stride conflict-free. acc[4][4] u64 = 32 regs (spill-safe).
// pd = 2*dot - sq_i - sq_j; top-16 per row, ties -> lower index.
// ---------------------------------------------------------------------------
template <int C>
__global__ void knn_kernel(const float* __restrict__ x, int lda,
                           const float* __restrict__ sq, int* __restrict__ outidx) {
    extern __shared__ float sm[];
    float* xiD = sm;                   // C x 136 (dup)
    float* xjT = sm + C * 136;         // C x 132 (xjT[c*132 + j], 128 j)
    float* pd  = xjT + C * 132;        // 64 x 132

    const int rowbase = blockIdx.y * NPTS;
    const int i0 = blockIdx.x * 64;
    const int tid = threadIdx.x;
    const int ty = tid >> 4, tx = tid & 15;
    const int srow = tid >> 2, sq4 = tid & 3;

    for (int t = tid; t < 64 * C; t += 256) {
        int i = t / C, c = t - i * C;
        float val = x[(long long)(rowbase + i0 + i) * lda + c];
        xiD[c * 136 + 2 * i] = val;
        xiD[c * 136 + 2 * i + 1] = val;
    }
    float sqi[4];
#pragma unroll
    for (int r = 0; r < 4; r++) sqi[r] = sq[rowbase + i0 + ty * 4 + r];

    float v[16]; int id[16];
#pragma unroll
    for (int q = 0; q < 16; q++) { v[q] = -CUDART_INF_F; id[q] = 0x7fffffff; }
    float vmin = -CUDART_INF_F; int vminid = 0x7fffffff; int minpos = 0;

    const float* xip = xiD + ty * 8;
    const float* xjp = xjT + tx * 4;   // strip A; strip B at +64

    for (int jt = 0; jt < NPTS / 128; jt++) {
        const int j0 = jt * 128;
        __syncthreads();   // prev tile consumers done
        for (int t = tid; t < 128 * C; t += 256) {
            int j = t / C, c = t - j * C;
            xjT[c * 132 + j] = x[(long long)(rowbase + j0 + j) * lda + c];
        }
        __syncthreads();

        u64 acc[4][4];
#pragma unroll
        for (int r = 0; r < 4; r++)
#pragma unroll
            for (int j = 0; j < 4; j++) acc[r][j] = 0ull;

#pragma unroll 4
        for (int c = 0; c < C; c++) {
            ulonglong2 a01 = *(const ulonglong2*)(xip + c * 136);
            ulonglong2 a23 = *(const ulonglong2*)(xip + c * 136 + 4);
            ulonglong2 bA = *(const ulonglong2*)(xjp + c * 132);        // j = tx*4..+3
            ulonglong2 bB = *(const ulonglong2*)(xjp + c * 132 + 64);   // j = 64+tx*4..+3
            ffma2(acc[0][0], a01.x, bA.x); ffma2(acc[0][1], a01.x, bA.y);
            ffma2(acc[0][2], a01.x, bB.x); ffma2(acc[0][3], a01.x, bB.y);
            ffma2(acc[1][0], a01.y, bA.x); ffma2(acc[1][1], a01.y, bA.y);
            ffma2(acc[1][2], a01.y, bB.x); ffma2(acc[1][3], a01.y, bB.y);
            ffma2(acc[2][0], a23.x, bA.x); ffma2(acc[2][1], a23.x, bA.y);
            ffma2(acc[2][2], a23.x, bB.x); ffma2(acc[2][3], a23.x, bB.y);
            ffma2(acc[3][0], a23.y, bA.x); ffma2(acc[3][1], a23.y, bA.y);
            ffma2(acc[3][2], a23.y, bB.x); ffma2(acc[3][3], a23.y, bB.y);
        }

        // epilogue: pd = 2*dot - sqi - sqj -> shared (two split strips)
        float4 sjA = *(const float4*)&sq[rowbase + j0 + tx * 4];
        float4 sjB = *(const float4*)&sq[rowbase + j0 + 64 + tx * 4];
#pragma unroll
        for (int r = 0; r < 4; r++) {
            float2 p0 = unpack2(acc[r][0]);
            float2 p1 = unpack2(acc[r][1]);
            float2 p2 = unpack2(acc[r][2]);
            float2 p3 = unpack2(acc[r][3]);
            float4 oA, oB;
            oA.x = 2.f * p0.x - sqi[r] - sjA.x;
            oA.y = 2.f * p0.y - sqi[r] - sjA.y;
            oA.z = 2.f * p1.x - sqi[r] - sjA.z;
            oA.w = 2.f * p1.y - sqi[r] - sjA.w;
            oB.x = 2.f * p2.x - sqi[r] - sjB.x;
            oB.y = 2.f * p2.y - sqi[r] - sjB.y;
            oB.z = 2.f * p3.x - sqi[r] - sjB.z;
            oB.w = 2.f * p3.y - sqi[r] - sjB.w;
            *(float4*)&pd[(ty * 4 + r) * 132 + tx * 4] = oA;
            *(float4*)&pd[(ty * 4 + r) * 132 + 64 + tx * 4] = oB;
        }
        __syncthreads();

        // selection: thread (srow, sq4) scans j strip [sq4*32, sq4*32+32)
#pragma unroll
        for (int s = 0; s < 8; s++) {
            const float4 pv = *(const float4*)&pd[srow * 132 + sq4 * 32 + s * 4];
            int jb = j0 + sq4 * 32 + s * 4;
            topk_ins(v, id, vmin, vminid, minpos, pv.x, jb);
            topk_ins(v, id, vmin, vminid, minpos, pv.y, jb + 1);
            topk_ins(v, id, vmin, vminid, minpos, pv.z, jb + 2);
            topk_ins(v, id, vmin, vminid, minpos, pv.w, jb + 3);
        }
    }

    // merge 4 lanes x 16 entries -> top-16 per row via warp shuffles
    for (int t = 0; t < KNN; t++) {
        float bv = -CUDART_INF_F; int bid = 0x7fffffff; int bq = 0;
#pragma unroll
        for (int q = 0; q < 16; q++) {
            bool w = (v[q] > bv) || (v[q] == bv && id[q] < bid);
            if (w) { bv = v[q]; bid = id[q]; bq = q; }
        }
        float lv = bv; int lid = bid;
#pragma unroll
        for (int off = 1; off < 4; off <<= 1) {
            float ov = __shfl_xor_sync(0xffffffffu, bv, off);
            int oid = __shfl_xor_sync(0xffffffffu, bid, off);
            if (ov > bv || (ov == bv && oid < bid)) { bv = ov; bid = oid; }
        }
        if (lid == bid && lv == bv) { v[bq] = -CUDART_INF_F; id[bq] = 0x7fffffff; }
        if (sq4 == 0) outidx[(long long)(rowbase + i0 + srow) * KNN + t] = bid;
    }
}

// ---------------------------------------------------------------------------
// SGEMM 64x64x16, 256 threads, 4x4 micro-tile in f32x2, double-buffered.
// (round-4 proven version)
// ---------------------------------------------------------------------------
__global__ void sgemm_kernel(const float* __restrict__ A, int lda,
                             const float* __restrict__ W, int K, int D, int dual,
                             float* __restrict__ Co, int ldc,
                             const float* __restrict__ bg, const float* __restrict__ bb,
                             const float* __restrict__ bm, const float* __restrict__ bvv) {
    __shared__ float As[2][16 * 136];
    __shared__ float Bs[2][16 * 68];
    const int mb = blockIdx.y * 64, nb = blockIdx.x * 64;
    const int tid = threadIdx.x;
    const int ry = tid >> 4, rx = tid & 15;
    u64 acc[4][2];
#pragma unroll
    for (int r = 0; r < 4; r++) { acc[r][0] = 0ull; acc[r][1] = 0ull; }
    float ra[4], rb[4];

#pragma unroll
    for (int u = 0; u < 4; u++) {
        int t = tid + u * 256; int m = t >> 4, k = t & 15;
        ra[u] = (k < K) ? A[(long long)(mb + m) * lda + k] : 0.f;
    }
#pragma unroll
    for (int u = 0; u < 4; u++) {
        int t = tid + u * 256; int k = t >> 6, n = t & 63;
        int gn = nb + n;
        float val = 0.f;
        if (k < K) {
            if (!dual) val = W[(long long)k * D + gn];
            else if (gn < D) val = W[(long long)k * D + gn];
            else val = W[(long long)(K + k) * D + gn - D];
        }
        rb[u] = val;
    }
#pragma unroll
    for (int u = 0; u < 4; u++) {
        int t = tid + u * 256;
        As[0][(t & 15) * 136 + 2 * (t >> 4)] = ra[u];
        As[0][(t & 15) * 136 + 2 * (t >> 4) + 1] = ra[u];
        Bs[0][(t >> 6) * 68 + (t & 63)] = rb[u];
    }
    __syncthreads();

    int p = 0;
    for (int kt = 0; kt < K; kt += 16) {
        const bool more = (kt + 16 < K);
        if (more) {
#pragma unroll
            for (int u = 0; u < 4; u++) {
                int t = tid + u * 256; int m = t >> 4, k = kt + 16 + (t & 15);
                ra[u] = (k < K) ? A[(long long)(mb + m) * lda + k] : 0.f;
            }
#pragma unroll
            for (int u = 0; u < 4; u++) {
                int t = tid + u * 256; int k = kt + 16 + (t >> 6), n = t & 63;
                int gn = nb + n;
                float val = 0.f;
                if (k < K) {
                    if (!dual) val = W[(long long)k * D + gn];
                    else if (gn < D) val = W[(long long)k * D + gn];
                    else val = W[(long long)(K + k) * D + gn - D];
                }
                rb[u] = val;
            }
        }
#pragma unroll
        for (int k = 0; k < 16; k++) {
            ulonglong2 a01 = *(const ulonglong2*)&As[p][k * 136 + ry * 8];
            ulonglong2 a23 = *(const ulonglong2*)&As[p][k * 136 + ry * 8 + 4];
            ulonglong2 bq  = *(const ulonglong2*)&Bs[p][k * 68 + rx * 4];
            ffma2(acc[0][0], a01.x, bq.x); ffma2(acc[0][1], a01.x, bq.y);
            ffma2(acc[1][0], a01.y, bq.x); ffma2(acc[1][1], a01.y, bq.y);
            ffma2(acc[2][0], a23.x, bq.x); ffma2(acc[2][1], a23.x, bq.y);
            ffma2(acc[3][0], a23.y, bq.x); ffma2(acc[3][1], a23.y, bq.y);
        }
        if (more) {
            __syncthreads();
#pragma unroll
            for (int u = 0; u < 4; u++) {
                int t = tid + u * 256;
                As[p ^ 1][(t & 15) * 136 + 2 * (t >> 4)] = ra[u];
                As[p ^ 1][(t & 15) * 136 + 2 * (t >> 4) + 1] = ra[u];
                Bs[p ^ 1][(t >> 6) * 68 + (t & 63)] = rb[u];
            }
            __syncthreads();
            p ^= 1;
        }
    }

    float out[4][4];
#pragma unroll
    for (int i = 0; i < 4; i++) {
        float2 lo = unpack2(acc[i][0]);
        float2 hi = unpack2(acc[i][1]);
        out[i][0] = lo.x; out[i][1] = lo.y; out[i][2] = hi.x; out[i][3] = hi.y;
    }
    if (bg) {
#pragma unroll
        for (int j = 0; j < 4; j++) {
            int n = nb + rx * 4 + j;
            float s = bg[n] * rsqrtf(bvv[n] + BN_EPS);
            float t = bb[n] - bm[n] * s;
#pragma unroll
            for (int i = 0; i < 4; i++) out[i][j] = fmaxf(fmaf(out[i][j], s, t), 0.f);
        }
    }
#pragma unroll
    for (int i = 0; i < 4; i++) {
        *(float4*)&Co[(long long)(mb + ry * 4 + i) * ldc + nb + rx * 4] =
            make_float4(out[i][0], out[i][1], out[i][2], out[i][3]);
    }
}

// ---------------------------------------------------------------------------
// gather + BN + ReLU + max over k=16; fused next-stage sqnorm. Warp per row.
// ---------------------------------------------------------------------------
__global__ void gathermax_kernel(const float* __restrict__ ytb, const int* __restrict__ idx,
                                 int D,
                                 const float* __restrict__ g, const float* __restrict__ b,
                                 const float* __restrict__ m, const float* __restrict__ vv,
                                 float* __restrict__ out, float* __restrict__ sqout) {
    const int warp = (blockIdx.x * blockDim.x + threadIdx.x) >> 5;
    const int lane = threadIdx.x & 31;
    if (warp >= NROWS) return;
    const int row = warp;
    const int base = row & ~(NPTS - 1);
    const int myid = idx[(long long)row * KNN + (lane & 15)];
    const float* top = ytb + (long long)row * 2 * D;
    float ss = 0.f;
    for (int c0 = 0; c0 < D; c0 += 64) {
        const int d = c0 + lane * 2;
        float2 g2 = *(const float2*)&g[d];
        float2 v2 = *(const float2*)&vv[d];
        float2 b2 = *(const float2*)&b[d];
        float2 m2 = *(const float2*)&m[d];
        float sx = g2.x * rsqrtf(v2.x + BN_EPS), txx = b2.x - m2.x * sx;
        float sy = g2.y * rsqrtf(v2.y + BN_EPS), tyy = b2.y - m2.y * sy;
        float2 tp = *(const float2*)&top[d];
        float bx = -CUDART_INF_F, by = -CUDART_INF_F;
#pragma unroll
        for (int k = 0; k < KNN; k++) {
            int sk = __shfl_sync(0xffffffffu, myid, k, 16);
            float2 yb = *(const float2*)&ytb[(long long)(base + sk) * 2 * D + D + d];
            bx = fmaxf(bx, fmaf(tp.x + yb.x, sx, txx));
            by = fmaxf(by, fmaf(tp.y + yb.y, sy, tyy));
        }
        bx = fmaxf(bx, 0.f); by = fmaxf(by, 0.f);
        *(float2*)&out[(long long)row * 512 + d] = make_float2(bx, by);
        ss += bx * bx + by * by;
    }
#pragma unroll
    for (int off = 16; off > 0; off >>= 1) ss += __shfl_down_sync(0xffffffffu, ss, off);
    if (lane == 0) sqout[row] = ss;
}

// ---------------------------------------------------------------------------
template <int C>
static void launch_knn(const float* in, int lda, const float* sqp, int* idxp) {
    size_t smem = (size_t)(C * 136 + C * 132 + 64 * 132) * 4;
    static bool done = false;
    if (!done) {
        cudaFuncSetAttribute(knn_kernel<C>, cudaFuncAttributeMaxDynamicSharedMemorySize,
                             (int)smem);
        done = true;
    }
    knn_kernel<C><<<dim3(NPTS / 64, NBATCH), 256, smem>>>(in, lda, sqp, idxp);
}

extern "C" void kernel_launch(void* const* d_in, const int* in_sizes, int n_in,
                              void* d_out, int out_size) {
    const float* x = (const float*)d_in[0];
    const float *W[5], *gg[5], *bb[5], *mm[5], *vv[5];
    for (int i = 0; i < 5; i++) {
        W[i]  = (const float*)d_in[1 + 5 * i];
        gg[i] = (const float*)d_in[2 + 5 * i];
        bb[i] = (const float*)d_in[3 + 5 * i];
        mm[i] = (const float*)d_in[4 + 5 * i];
        vv[i] = (const float*)d_in[5 + 5 * i];
    }
    float *xcat, *ytb, *sqp; int* idxp;
    cudaGetSymbolAddress((void**)&xcat, g_xcat);
    cudaGetSymbolAddress((void**)&ytb, g_ytb);
    cudaGetSymbolAddress((void**)&sqp, g_sq);
    cudaGetSymbolAddress((void**)&idxp, g_idx);

    const int Cs[4] = {3, 64, 64, 128};
    const int Ds[4] = {64, 64, 128, 256};

    sqnorm_kernel<<<NROWS / 256, 256>>>(x, 3, 3, sqp);

    const float* in = x;
    int lda = 3;
    int coloff = 0;
    for (int s = 0; s < 4; s++) {
        const int C = Cs[s], D = Ds[s];
        if (C == 3)        launch_knn<3>(in, lda, sqp, idxp);
        else if (C == 64)  launch_knn<64>(in, lda, sqp, idxp);
        else               launch_knn<128>(in, lda, sqp, idxp);
        sgemm_kernel<<<dim3(2 * D / 64, NROWS / 64), 256>>>(in, lda, W[s], C, D, 1,
                                                            ytb, 2 * D,
                                                            nullptr, nullptr, nullptr, nullptr);
        float* outp = xcat + coloff;
        gathermax_kernel<<<NROWS / 8, 256>>>(ytb, idxp, D, gg[s], bb[s], mm[s], vv[s],
                                             outp, sqp);
        in = outp; lda = 512;
        coloff += D;
    }
    sgemm_kernel<<<dim3(512 / 64, NROWS / 64), 256>>>(xcat, 512, W[4], 512, 512, 0,
                                                      (float*)d_out, 512,
                                                      gg[4], bb[4], mm[4], vv[4]);
}

// round 8
// speedup vs baseline: 5.1126x; 1.5545x over previous
#include <cuda_runtime.h>
#include <math_constants.h>

#define BN_EPS 1e-3f
#define NPTS 2048
#define NBATCH 8
#define NROWS (NPTS * NBATCH)
#define KNN 16
#define NSPLIT 2

typedef unsigned long long u64;

__device__ float g_xcat[NROWS * 512];
__device__ float g_ytb[NROWS * 512];
__device__ float g_sq[NROWS];
__device__ int   g_idx[NROWS * KNN];
__device__ float g_cv[NROWS * KNN * NSPLIT];
__device__ int   g_ci[NROWS * KNN * NSPLIT];

// ---------------- f32x2 packed helpers (FFMA2: 2x fp32 throughput) ----------
__device__ __forceinline__ void ffma2(u64& d, u64 a, u64 b) {
    asm("fma.rn.f32x2 %0, %1, %2, %0;" : "+l"(d) : "l"(a), "l"(b));
}
__device__ __forceinline__ float2 unpack2(u64 v) {
    float2 r;
    asm("mov.b64 {%0, %1}, %2;" : "=f"(r.x), "=f"(r.y) : "l"(v));
    return r;
}

// ---------------------------------------------------------------------------
__global__ void sqnorm_kernel(const float* __restrict__ x, int lda, int C,
                              float* __restrict__ sq) {
    int i = blockIdx.x * blockDim.x + threadIdx.x;
    if (i < NROWS) {
        const float* p = x + (long long)i * lda;
        float s = 0.f;
        for (int c = 0; c < C; c++) { float v = p[c]; s = fmaf(v, v, s); }
        sq[i] = s;
    }
}

// ---------------------------------------------------------------------------
__device__ __forceinline__ void topk_ins(float (&v)[16], int (&id)[16],
                                         float& vmin, int& vminid, int& minpos,
                                         float pv, int jg) {
    if (pv > vmin || (pv == vmin && jg < vminid)) {
#pragma unroll
        for (int q = 0; q < 16; q++)
            if (q == minpos) { v[q] = pv; id[q] = jg; }
        vmin = v[0]; vminid = id[0]; minpos = 0;
#pragma unroll
        for (int q = 1; q < 16; q++) {
            bool w = (v[q] < vmin) || (v[q] == vmin && id[q] > vminid);
            if (w) { vmin = v[q]; vminid = id[q]; minpos = q; }
        }
    }
}

// ---------------------------------------------------------------------------
// kNN (split): each block handles 64 i-rows x (NPTS/NSPLIT) j-range, 64-j
// tiles, 256 threads, 4x4 micro-tile in f32x2 (R4-proven inner loop).
// pd aliases the xjT buffer (xjT dead when pd written) -> smem small enough
// for 2 blocks/SM at C=128 (4 at C=64). Emits exact per-split top-16.
// ---------------------------------------------------------------------------
template <int C>
__global__ void knn_kernel(const float* __restrict__ x, int lda,
                           const float* __restrict__ sq,
                           float* __restrict__ outcv, int* __restrict__ outci) {
    constexpr int BUFROWS = (C > 64) ? C : 64;
    extern __shared__ float sm[];
    float* xiD = sm;                    // C x 136 (dup: (v,v) pairs)
    float* buf = sm + C * 136;          // BUFROWS x 68: xjT then pd (aliased)

    const int rowbase = blockIdx.y * NPTS;
    const int i0 = blockIdx.x * 64;
    const int spbase = blockIdx.z * (NPTS / NSPLIT);
    const int tid = threadIdx.x;
    const int ty = tid >> 4, tx = tid & 15;
    const int srow = tid >> 2, sq4 = tid & 3;

    for (int t = tid; t < 64 * C; t += 256) {
        int i = t / C, c = t - i * C;
        float val = x[(long long)(rowbase + i0 + i) * lda + c];
        xiD[c * 136 + 2 * i] = val;
        xiD[c * 136 + 2 * i + 1] = val;
    }
    float sqi[4];
#pragma unroll
    for (int r = 0; r < 4; r++) sqi[r] = sq[rowbase + i0 + ty * 4 + r];

    float v[16]; int id[16];
#pragma unroll
    for (int q = 0; q < 16; q++) { v[q] = -CUDART_INF_F; id[q] = 0x7fffffff; }
    float vmin = -CUDART_INF_F; int vminid = 0x7fffffff; int minpos = 0;

    const float* xip = xiD + ty * 8;
    const float* xjp = buf + tx * 4;

    for (int jt = 0; jt < NPTS / NSPLIT / 64; jt++) {
        const int j0 = spbase + jt * 64;
        __syncthreads();   // prev selection (pd reads) done
        for (int t = tid; t < 64 * C; t += 256) {
            int j = t / C, c = t - j * C;
            buf[c * 68 + j] = x[(long long)(rowbase + j0 + j) * lda + c];
        }
        __syncthreads();

        u64 acc[4][2];
#pragma unroll
        for (int r = 0; r < 4; r++) { acc[r][0] = 0ull; acc[r][1] = 0ull; }

#pragma unroll 4
        for (int c = 0; c < C; c++) {
            ulonglong2 a01 = *(const ulonglong2*)(xip + c * 136);
            ulonglong2 a23 = *(const ulonglong2*)(xip + c * 136 + 4);
            ulonglong2 bq  = *(const ulonglong2*)(xjp + c * 68);
            ffma2(acc[0][0], a01.x, bq.x); ffma2(acc[0][1], a01.x, bq.y);
            ffma2(acc[1][0], a01.y, bq.x); ffma2(acc[1][1], a01.y, bq.y);
            ffma2(acc[2][0], a23.x, bq.x); ffma2(acc[2][1], a23.x, bq.y);
            ffma2(acc[3][0], a23.y, bq.x); ffma2(acc[3][1], a23.y, bq.y);
        }
        __syncthreads();   // all xjT reads done before pd overwrites buf

        float4 sj = *(const float4*)&sq[rowbase + j0 + tx * 4];
#pragma unroll
        for (int r = 0; r < 4; r++) {
            float2 lo = unpack2(acc[r][0]);
            float2 hi = unpack2(acc[r][1]);
            float4 o;
            o.x = 2.f * lo.x - sqi[r] - sj.x;
            o.y = 2.f * lo.y - sqi[r] - sj.y;
            o.z = 2.f * hi.x - sqi[r] - sj.z;
            o.w = 2.f * hi.y - sqi[r] - sj.w;
            *(float4*)&buf[(ty * 4 + r) * 68 + tx * 4] = o;   // pd
        }
        __syncthreads();

        // selection: thread (srow, sq4) scans j strip [sq4*16, sq4*16+16)
#pragma unroll
        for (int s = 0; s < 4; s++) {
            const float4 pv = *(const float4*)&buf[srow * 68 + sq4 * 16 + s * 4];
            int jb = j0 + sq4 * 16 + s * 4;
            topk_ins(v, id, vmin, vminid, minpos, pv.x, jb);
            topk_ins(v, id, vmin, vminid, minpos, pv.y, jb + 1);
            topk_ins(v, id, vmin, vminid, minpos, pv.z, jb + 2);
            topk_ins(v, id, vmin, vminid, minpos, pv.w, jb + 3);
        }
    }

    // merge 4 lanes x 16 entries -> top-16 per row via warp shuffles
    const long long crow = (long long)(rowbase + i0 + srow) * (KNN * NSPLIT)
                           + blockIdx.z * KNN;
    for (int t = 0; t < KNN; t++) {
        float bv = -CUDART_INF_F; int bid = 0x7fffffff; int bq = 0;
#pragma unroll
        for (int q = 0; q < 16; q++) {
            bool w = (v[q] > bv) || (v[q] == bv && id[q] < bid);
            if (w) { bv = v[q]; bid = id[q]; bq = q; }
        }
        float lv = bv; int lid = bid;
#pragma unroll
        for (int off = 1; off < 4; off <<= 1) {
            float ov = __shfl_xor_sync(0xffffffffu, bv, off);
            int oid = __shfl_xor_sync(0xffffffffu, bid, off);
            if (ov > bv || (ov == bv && oid < bid)) { bv = ov; bid = oid; }
        }
        if (lid == bid && lv == bv) { v[bq] = -CUDART_INF_F; id[bq] = 0x7fffffff; }
        if (sq4 == 0) { outcv[crow + t] = bv; outci[crow + t] = bid; }
    }
}

// ---------------------------------------------------------------------------
// merge NSPLIT x 16 candidates -> global top-16 per row. One warp per row.
// Rank by (v desc, id asc); ids are distinct so ranks are unique.
// ---------------------------------------------------------------------------
__global__ void knnmerge_kernel(const float* __restrict__ cv, const int* __restrict__ ci,
                                int* __restrict__ outidx) {
    const int row = blockIdx.x * (blockDim.x >> 5) + (threadIdx.x >> 5);
    const int lane = threadIdx.x & 31;
    float v = cv[(long long)row * 32 + lane];
    int id = ci[(long long)row * 32 + lane];
    int rank = 0;
#pragma unroll
    for (int o = 0; o < 32; o++) {
        float ov = __shfl_sync(0xffffffffu, v, o);
        int oid = __shfl_sync(0xffffffffu, id, o);
        if (ov > v || (ov == v && oid < id)) rank++;
    }
    if (rank < KNN) outidx[(long long)row * KNN + rank] = id;
}

// ---------------------------------------------------------------------------
// SGEMM 64x64x16, 256 threads, 4x4 micro-tile in f32x2, double-buffered.
// (round-4 proven version)
// ---------------------------------------------------------------------------
__global__ void sgemm_kernel(const float* __restrict__ A, int lda,
                             const float* __restrict__ W, int K, int D, int dual,
                             float* __restrict__ Co, int ldc,
                             const float* __restrict__ bg, const float* __restrict__ bb,
                             const float* __restrict__ bm, const float* __restrict__ bvv) {
    __shared__ float As[2][16 * 136];
    __shared__ float Bs[2][16 * 68];
    const int mb = blockIdx.y * 64, nb = blockIdx.x * 64;
    const int tid = threadIdx.x;
    const int ry = tid >> 4, rx = tid & 15;
    u64 acc[4][2];
#pragma unroll
    for (int r = 0; r < 4; r++) { acc[r][0] = 0ull; acc[r][1] = 0ull; }
    float ra[4], rb[4];

#pragma unroll
    for (int u = 0; u < 4; u++) {
        int t = tid + u * 256; int m = t >> 4, k = t & 15;
        ra[u] = (k < K) ? A[(long long)(mb + m) * lda + k] : 0.f;
    }
#pragma unroll
    for (int u = 0; u < 4; u++) {
        int t = tid + u * 256; int k = t >> 6, n = t & 63;
        int gn = nb + n;
        float val = 0.f;
        if (k < K) {
            if (!dual) val = W[(long long)k * D + gn];
            else if (gn < D) val = W[(long long)k * D + gn];
            else val = W[(long long)(K + k) * D + gn - D];
        }
        rb[u] = val;
    }
#pragma unroll
    for (int u = 0; u < 4; u++) {
        int t = tid + u * 256;
        As[0][(t & 15) * 136 + 2 * (t >> 4)] = ra[u];
        As[0][(t & 15) * 136 + 2 * (t >> 4) + 1] = ra[u];
        Bs[0][(t >> 6) * 68 + (t & 63)] = rb[u];
    }
    __syncthreads();

    int p = 0;
    for (int kt = 0; kt < K; kt += 16) {
        const bool more = (kt + 16 < K);
        if (more) {
#pragma unroll
            for (int u = 0; u < 4; u++) {
                int t = tid + u * 256; int m = t >> 4, k = kt + 16 + (t & 15);
                ra[u] = (k < K) ? A[(long long)(mb + m) * lda + k] : 0.f;
            }
#pragma unroll
            for (int u = 0; u < 4; u++) {
                int t = tid + u * 256; int k = kt + 16 + (t >> 6), n = t & 63;
                int gn = nb + n;
                float val = 0.f;
                if (k < K) {
                    if (!dual) val = W[(long long)k * D + gn];
                    else if (gn < D) val = W[(long long)k * D + gn];
                    else val = W[(long long)(K + k) * D + gn - D];
                }
                rb[u] = val;
            }
        }
#pragma unroll
        for (int k = 0; k < 16; k++) {
            ulonglong2 a01 = *(const ulonglong2*)&As[p][k * 136 + ry * 8];
            ulonglong2 a23 = *(const ulonglong2*)&As[p][k * 136 + ry * 8 + 4];
            ulonglong2 bq  = *(const ulonglong2*)&Bs[p][k * 68 + rx * 4];
            ffma2(acc[0][0], a01.x, bq.x); ffma2(acc[0][1], a01.x, bq.y);
            ffma2(acc[1][0], a01.y, bq.x); ffma2(acc[1][1], a01.y, bq.y);
            ffma2(acc[2][0], a23.x, bq.x); ffma2(acc[2][1], a23.x, bq.y);
            ffma2(acc[3][0], a23.y, bq.x); ffma2(acc[3][1], a23.y, bq.y);
        }
        if (more) {
            __syncthreads();
#pragma unroll
            for (int u = 0; u < 4; u++) {
                int t = tid + u * 256;
                As[p ^ 1][(t & 15) * 136 + 2 * (t >> 4)] = ra[u];
                As[p ^ 1][(t & 15) * 136 + 2 * (t >> 4) + 1] = ra[u];
                Bs[p ^ 1][(t >> 6) * 68 + (t & 63)] = rb[u];
            }
            __syncthreads();
            p ^= 1;
        }
    }

    float out[4][4];
#pragma unroll
    for (int i = 0; i < 4; i++) {
        float2 lo = unpack2(acc[i][0]);
        float2 hi = unpack2(acc[i][1]);
        out[i][0] = lo.x; out[i][1] = lo.y; out[i][2] = hi.x; out[i][3] = hi.y;
    }
    if (bg) {
#pragma unroll
        for (int j = 0; j < 4; j++) {
            int n = nb + rx * 4 + j;
            float s = bg[n] * rsqrtf(bvv[n] + BN_EPS);
            float t = bb[n] - bm[n] * s;
#pragma unroll
            for (int i = 0; i < 4; i++) out[i][j] = fmaxf(fmaf(out[i][j], s, t), 0.f);
        }
    }
#pragma unroll
    for (int i = 0; i < 4; i++) {
        *(float4*)&Co[(long long)(mb + ry * 4 + i) * ldc + nb + rx * 4] =
            make_float4(out[i][0], out[i][1], out[i][2], out[i][3]);
    }
}

// ---------------------------------------------------------------------------
// gather + BN + ReLU + max over k=16; fused next-stage sqnorm. Warp per row.
// ---------------------------------------------------------------------------
__global__ void gathermax_kernel(const float* __restrict__ ytb, const int* __restrict__ idx,
                                 int D,
                                 const float* __restrict__ g, const float* __restrict__ b,
                                 const float* __restrict__ m, const float* __restrict__ vv,
                                 float* __restrict__ out, float* __restrict__ sqout) {
    const int warp = (blockIdx.x * blockDim.x + threadIdx.x) >> 5;
    const int lane = threadIdx.x & 31;
    if (warp >= NROWS) return;
    const int row = warp;
    const int base = row & ~(NPTS - 1);
    const int myid = idx[(long long)row * KNN + (lane & 15)];
    const float* top = ytb + (long long)row * 2 * D;
    float ss = 0.f;
    for (int c0 = 0; c0 < D; c0 += 64) {
        const int d = c0 + lane * 2;
        float2 g2 = *(const float2*)&g[d];
        float2 v2 = *(const float2*)&vv[d];
        float2 b2 = *(const float2*)&b[d];
        float2 m2 = *(const float2*)&m[d];
        float sx = g2.x * rsqrtf(v2.x + BN_EPS), txx = b2.x - m2.x * sx;
        float sy = g2.y * rsqrtf(v2.y + BN_EPS), tyy = b2.y - m2.y * sy;
        float2 tp = *(const float2*)&top[d];
        float bx = -CUDART_INF_F, by = -CUDART_INF_F;
#pragma unroll
        for (int k = 0; k < KNN; k++) {
            int sk = __shfl_sync(0xffffffffu, myid, k, 16);
            float2 yb = *(const float2*)&ytb[(long long)(base + sk) * 2 * D + D + d];
            bx = fmaxf(bx, fmaf(tp.x + yb.x, sx, txx));
            by = fmaxf(by, fmaf(tp.y + yb.y, sy, tyy));
        }
        bx = fmaxf(bx, 0.f); by = fmaxf(by, 0.f);
        *(float2*)&out[(long long)row * 512 + d] = make_float2(bx, by);
        ss += bx * bx + by * by;
    }
#pragma unroll
    for (int off = 16; off > 0; off >>= 1) ss += __shfl_down_sync(0xffffffffu, ss, off);
    if (lane == 0) sqout[row] = ss;
}

// ---------------------------------------------------------------------------
template <int C>
static void launch_knn(const float* in, int lda, const float* sqp,
                       float* cvp, int* cip, int* idxp) {
    constexpr int BUFROWS = (C > 64) ? C : 64;
    size_t smem = (size_t)(C * 136 + BUFROWS * 68) * 4;
    static bool done = false;
    if (!done) {
        cudaFuncSetAttribute(knn_kernel<C>, cudaFuncAttributeMaxDynamicSharedMemorySize,
                             (int)smem);
        done = true;
    }
    knn_kernel<C><<<dim3(NPTS / 64, NBATCH, NSPLIT), 256, smem>>>(in, lda, sqp, cvp, cip);
    knnmerge_kernel<<<NROWS / 8, 256>>>(cvp, cip, idxp);
}

extern "C" void kernel_launch(void* const* d_in, const int* in_sizes, int n_in,
                              void* d_out, int out_size) {
    const float* x = (const float*)d_in[0];
    const float *W[5], *gg[5], *bb[5], *mm[5], *vv[5];
    for (int i = 0; i < 5; i++) {
        W[i]  = (const float*)d_in[1 + 5 * i];
        gg[i] = (const float*)d_in[2 + 5 * i];
        bb[i] = (const float*)d_in[3 + 5 * i];
        mm[i] = (const float*)d_in[4 + 5 * i];
        vv[i] = (const float*)d_in[5 + 5 * i];
    }
    float *xcat, *ytb, *sqp, *cvp; int *idxp, *cip;
    cudaGetSymbolAddress((void**)&xcat, g_xcat);
    cudaGetSymbolAddress((void**)&ytb, g_ytb);
    cudaGetSymbolAddress((void**)&sqp, g_sq);
    cudaGetSymbolAddress((void**)&idxp, g_idx);
    cudaGetSymbolAddress((void**)&cvp, g_cv);
    cudaGetSymbolAddress((void**)&cip, g_ci);

    const int Cs[4] = {3, 64, 64, 128};
    const int Ds[4] = {64, 64, 128, 256};

    sqnorm_kernel<<<NROWS / 256, 256>>>(x, 3, 3, sqp);

    const float* in = x;
    int lda = 3;
    int coloff = 0;
    for (int s = 0; s < 4; s++) {
        const int C = Cs[s], D = Ds[s];
        if (C == 3)        launch_knn<3>(in, lda, sqp, cvp, cip, idxp);
        else if (C == 64)  launch_knn<64>(in, lda, sqp, cvp, cip, idxp);
        else               launch_knn<128>(in, lda, sqp, cvp, cip, idxp);
        sgemm_kernel<<<dim3(2 * D / 64, NROWS / 64), 256>>>(in, lda, W[s], C, D, 1,
                                                            ytb, 2 * D,
                                                            nullptr, nullptr, nullptr, nullptr);
        float* outp = xcat + coloff;
        gathermax_kernel<<<NROWS / 8, 256>>>(ytb, idxp, D, gg[s], bb[s], mm[s], vv[s],
                                             outp, sqp);
        in = outp; lda = 512;
        coloff += D;
    }
    sgemm_kernel<<<dim3(512 / 64, NROWS / 64), 256>>>(xcat, 512, W[4], 512, 512, 0,
                                                      (float*)d_out, 512,
                                                      gg[4], bb[4], mm[4], vv[4]);
}